// round 1
// baseline (speedup 1.0000x reference)
#include <cuda_runtime.h>

// Problem constants
#define B_    4
#define N_    2048
#define DIN   1024
#define NH_   16
#define HD_   64
#define BH_   (B_ * NH_)      // 64
#define DMODEL (NH_ * HD_)    // 1024

// Scratch: Q/K/V in [bh][n][d] layout, 32 MB each.
__device__ float g_qkv[3][(size_t)BH_ * N_ * HD_];

// ---------------------------------------------------------------------------
// Projection GEMM: C = X * W^T, written remapped to [b][h][n][d].
// X: [8192, 1024] row-major, W: [1024, 1024] row-major (torch Linear [out,in]).
// Tiling: 128x128 block, K-tile 8, 256 threads, 8x8 per thread.
// ---------------------------------------------------------------------------
__global__ __launch_bounds__(256) void proj_kernel(const float* __restrict__ X,
                                                   const float* __restrict__ W,
                                                   int which) {
    __shared__ float As[8][128];
    __shared__ float Bs[8][128];

    float* out = g_qkv[which];

    const int tid = threadIdx.x;
    const int tx = tid & 15;         // 0..15 -> N cols
    const int ty = tid >> 4;         // 0..15 -> M rows
    const int m0 = blockIdx.y * 128;
    const int n0 = blockIdx.x * 128;

    float acc[8][8];
#pragma unroll
    for (int i = 0; i < 8; i++)
#pragma unroll
        for (int j = 0; j < 8; j++) acc[i][j] = 0.0f;

    const int lrow = tid >> 1;        // 0..127
    const int lcol = (tid & 1) * 4;   // 0 or 4
    const float* xg = X + (size_t)(m0 + lrow) * DIN + lcol;
    const float* wg = W + (size_t)(n0 + lrow) * DIN + lcol;

    for (int k0 = 0; k0 < DIN; k0 += 8) {
        float4 av = *(const float4*)(xg + k0);
        float4 bv = *(const float4*)(wg + k0);
        As[lcol + 0][lrow] = av.x; As[lcol + 1][lrow] = av.y;
        As[lcol + 2][lrow] = av.z; As[lcol + 3][lrow] = av.w;
        Bs[lcol + 0][lrow] = bv.x; Bs[lcol + 1][lrow] = bv.y;
        Bs[lcol + 2][lrow] = bv.z; Bs[lcol + 3][lrow] = bv.w;
        __syncthreads();
#pragma unroll
        for (int k = 0; k < 8; k++) {
            float a[8], b[8];
#pragma unroll
            for (int i = 0; i < 8; i++) a[i] = As[k][ty * 8 + i];
#pragma unroll
            for (int j = 0; j < 8; j++) b[j] = Bs[k][tx * 8 + j];
#pragma unroll
            for (int i = 0; i < 8; i++)
#pragma unroll
                for (int j = 0; j < 8; j++)
                    acc[i][j] = fmaf(a[i], b[j], acc[i][j]);
        }
        __syncthreads();
    }

    // Epilogue: out[(b*NH + h)][n][d], o = h*64+d. 8-wide col chunks stay
    // inside one head (8-aligned within 64).
#pragma unroll
    for (int i = 0; i < 8; i++) {
        int m = m0 + ty * 8 + i;
        int bb = m >> 11;             // /2048
        int n  = m & (N_ - 1);
#pragma unroll
        for (int j = 0; j < 8; j++) {
            int o = n0 + tx * 8 + j;
            int h = o >> 6;
            int d = o & 63;
            out[(((size_t)(bb * NH_ + h)) * N_ + n) * HD_ + d] = acc[i][j];
        }
    }
}

// ---------------------------------------------------------------------------
// Flash-style attention: per (bh, q-block of 64) CTA, loop over 32 KV tiles.
// 256 threads as 16x16; each thread owns a 4x4 S/P patch and a 4x4 O patch.
// All smem tiles [64 rows][pitch 65] natural layout; <=2-way conflicts.
// ---------------------------------------------------------------------------
#define RPAD 65
#define ATT_SMEM (3 * 64 * RPAD * 4)

__global__ __launch_bounds__(256) void attn_kernel(float* __restrict__ out) {
    extern __shared__ float sm[];
    float* Qs  = sm;                   // [64][RPAD]  Q tile  [m][d]
    float* KPs = sm + 64 * RPAD;       // [64][RPAD]  K tile [n][d], reused as P [i][j]
    float* Vs  = sm + 2 * 64 * RPAD;   // [64][RPAD]  V tile  [n][d]

    const float* Q = g_qkv[0];
    const float* K = g_qkv[1];
    const float* V = g_qkv[2];

    const int tid = threadIdx.x;
    const int tx = tid & 15;           // col group
    const int ty = tid >> 4;           // row group
    const int qb = blockIdx.x;         // 0..31
    const int bh = blockIdx.y;         // 0..63

    const float* Qg = Q + ((size_t)bh * N_ + qb * 64) * HD_;
    const float* Kg = K + (size_t)bh * N_ * HD_;
    const float* Vg = V + (size_t)bh * N_ * HD_;

    // Load Q tile once.
    {
        int r = tid >> 4;              // 0..15
        int c = (tid & 15) * 4;        // 0..60
#pragma unroll
        for (int rr = 0; rr < 4; rr++) {
            int m = rr * 16 + r;
            float4 v = *(const float4*)(Qg + (size_t)m * HD_ + c);
            Qs[m * RPAD + c + 0] = v.x; Qs[m * RPAD + c + 1] = v.y;
            Qs[m * RPAD + c + 2] = v.z; Qs[m * RPAD + c + 3] = v.w;
        }
    }

    float oacc[4][4];
#pragma unroll
    for (int i = 0; i < 4; i++)
#pragma unroll
        for (int j = 0; j < 4; j++) oacc[i][j] = 0.0f;

    float mstat[4], lstat[4];
#pragma unroll
    for (int i = 0; i < 4; i++) { mstat[i] = -1e30f; lstat[i] = 0.0f; }

    const float scale = 0.125f;        // 1/sqrt(64)

    for (int kt = 0; kt < N_ / 64; kt++) {
        __syncthreads();               // prior iter's P/V reads done
        // Load K and V tiles.
        {
            int r = tid >> 4;
            int c = (tid & 15) * 4;
#pragma unroll
            for (int rr = 0; rr < 4; rr++) {
                int m = rr * 16 + r;
                float4 kv = *(const float4*)(Kg + (size_t)(kt * 64 + m) * HD_ + c);
                float4 vv = *(const float4*)(Vg + (size_t)(kt * 64 + m) * HD_ + c);
                KPs[m * RPAD + c + 0] = kv.x; KPs[m * RPAD + c + 1] = kv.y;
                KPs[m * RPAD + c + 2] = kv.z; KPs[m * RPAD + c + 3] = kv.w;
                Vs[m * RPAD + c + 0] = vv.x; Vs[m * RPAD + c + 1] = vv.y;
                Vs[m * RPAD + c + 2] = vv.z; Vs[m * RPAD + c + 3] = vv.w;
            }
        }
        __syncthreads();

        // S = scale * Q K^T (4x4 per thread)
        float s[4][4];
#pragma unroll
        for (int i = 0; i < 4; i++)
#pragma unroll
            for (int j = 0; j < 4; j++) s[i][j] = 0.0f;

#pragma unroll 8
        for (int d = 0; d < HD_; d++) {
            float a[4], b[4];
#pragma unroll
            for (int i = 0; i < 4; i++) a[i] = Qs[(ty * 4 + i) * RPAD + d];
#pragma unroll
            for (int j = 0; j < 4; j++) b[j] = KPs[(tx * 4 + j) * RPAD + d];
#pragma unroll
            for (int i = 0; i < 4; i++)
#pragma unroll
                for (int j = 0; j < 4; j++)
                    s[i][j] = fmaf(a[i], b[j], s[i][j]);
        }
#pragma unroll
        for (int i = 0; i < 4; i++)
#pragma unroll
            for (int j = 0; j < 4; j++) s[i][j] *= scale;

        // Row max over full 64-wide row (reduce over 16-lane tx group).
        float rm[4];
#pragma unroll
        for (int i = 0; i < 4; i++) {
            float v = fmaxf(fmaxf(s[i][0], s[i][1]), fmaxf(s[i][2], s[i][3]));
#pragma unroll
            for (int off = 1; off < 16; off <<= 1)
                v = fmaxf(v, __shfl_xor_sync(0xffffffffu, v, off));
            rm[i] = v;
        }

        float corr[4];
#pragma unroll
        for (int i = 0; i < 4; i++) {
            float nm = fmaxf(mstat[i], rm[i]);
            corr[i] = __expf(mstat[i] - nm);
            mstat[i] = nm;
        }

        float rs[4];
#pragma unroll
        for (int i = 0; i < 4; i++) {
            float acc = 0.0f;
#pragma unroll
            for (int j = 0; j < 4; j++) {
                s[i][j] = __expf(s[i][j] - mstat[i]);
                acc += s[i][j];
            }
#pragma unroll
            for (int off = 1; off < 16; off <<= 1)
                acc += __shfl_xor_sync(0xffffffffu, acc, off);
            rs[i] = acc;
        }

#pragma unroll
        for (int i = 0; i < 4; i++) {
            lstat[i] = lstat[i] * corr[i] + rs[i];
#pragma unroll
            for (int dd = 0; dd < 4; dd++) oacc[i][dd] *= corr[i];
        }

        __syncthreads();               // all K reads done before P overwrite
        // Write P into the K buffer.
#pragma unroll
        for (int i = 0; i < 4; i++)
#pragma unroll
            for (int j = 0; j < 4; j++)
                KPs[(ty * 4 + i) * RPAD + tx * 4 + j] = s[i][j];
        __syncthreads();

        // O += P V  (inner loop over j)
#pragma unroll 8
        for (int j = 0; j < 64; j++) {
            float a[4], b[4];
#pragma unroll
            for (int i = 0; i < 4; i++) a[i] = KPs[(ty * 4 + i) * RPAD + j];
#pragma unroll
            for (int dd = 0; dd < 4; dd++) b[dd] = Vs[j * RPAD + tx * 4 + dd];
#pragma unroll
            for (int i = 0; i < 4; i++)
#pragma unroll
                for (int dd = 0; dd < 4; dd++)
                    oacc[i][dd] = fmaf(a[i], b[dd], oacc[i][dd]);
        }
    }

    // Final normalize + write: out[b][n][h*64+d]
    const int bb = bh >> 4;
    const int h  = bh & 15;
#pragma unroll
    for (int i = 0; i < 4; i++) {
        int n = qb * 64 + ty * 4 + i;
        float inv = 1.0f / lstat[i];
        size_t base = ((size_t)bb * N_ + n) * DMODEL + h * HD_ + tx * 4;
#pragma unroll
        for (int dd = 0; dd < 4; dd++)
            out[base + dd] = oacc[i][dd] * inv;
    }
}

// ---------------------------------------------------------------------------
// Launch: 3 projection GEMMs + attention. Inputs: x, attn_mask(unused),
// Wq, Wk, Wv. Output fp32 [B, N, 1024].
// ---------------------------------------------------------------------------
extern "C" void kernel_launch(void* const* d_in, const int* in_sizes, int n_in,
                              void* d_out, int out_size) {
    const float* x  = (const float*)d_in[0];
    const float* Wq = (const float*)d_in[2];
    const float* Wk = (const float*)d_in[3];
    const float* Wv = (const float*)d_in[4];
    float* out = (float*)d_out;
    (void)in_sizes; (void)n_in; (void)out_size;

    cudaFuncSetAttribute(attn_kernel,
                         cudaFuncAttributeMaxDynamicSharedMemorySize, ATT_SMEM);

    dim3 pgrid(DMODEL / 128, (B_ * N_) / 128);   // (8, 64)
    proj_kernel<<<pgrid, 256>>>(x, Wq, 0);
    proj_kernel<<<pgrid, 256>>>(x, Wk, 1);
    proj_kernel<<<pgrid, 256>>>(x, Wv, 2);

    dim3 agrid(N_ / 64, BH_);                    // (32, 64)
    attn_kernel<<<agrid, 256, ATT_SMEM>>>(out);
}

// round 2
// speedup vs baseline: 3.1031x; 3.1031x over previous
#include <cuda_runtime.h>
#include <cstdint>

#define B_    4
#define N_    2048
#define DIN   1024
#define NH_   16
#define HD_   64
#define BH_   (B_ * NH_)      // 64
#define DMODEL (NH_ * HD_)    // 1024

// Scratch: Q/K/V in [bh][n][d] layout (tf32-rounded fp32), 32 MB each.
__device__ float g_qkv[3][(size_t)BH_ * N_ * HD_];

// ---------------------------------------------------------------------------
// Helpers
// ---------------------------------------------------------------------------
__device__ __forceinline__ float f2tf32(float f) {
    unsigned u;
    asm("cvt.rna.tf32.f32 %0, %1;" : "=r"(u) : "f"(f));
    return __uint_as_float(u);
}

__device__ __forceinline__ void mma_tf32(float c[4],
                                         unsigned a0, unsigned a1,
                                         unsigned a2, unsigned a3,
                                         unsigned b0, unsigned b1) {
    asm volatile(
        "mma.sync.aligned.m16n8k8.row.col.f32.tf32.tf32.f32 "
        "{%0,%1,%2,%3}, {%4,%5,%6,%7}, {%8,%9}, {%0,%1,%2,%3};"
        : "+f"(c[0]), "+f"(c[1]), "+f"(c[2]), "+f"(c[3])
        : "r"(a0), "r"(a1), "r"(a2), "r"(a3), "r"(b0), "r"(b1));
}

// ---------------------------------------------------------------------------
// Projection GEMM (tf32 mma): C = X * W^T remapped to [bh][n][d].
// CTA 128x128, K-chunk 64, 8 warps in 4(m) x 2(n); warp tile 32x64.
// Smem pitch 68 (== 4 mod 32) -> conflict-free fragment reads.
// ---------------------------------------------------------------------------
#define PJP 68
#define PROJ_SMEM (2 * 128 * PJP * 4)

__global__ __launch_bounds__(256) void proj_mma(const float* __restrict__ X,
                                                const float* __restrict__ W,
                                                int which) {
    extern __shared__ float sm[];
    float* As = sm;                 // [128][PJP]  X tile, k-major rows
    float* Bs = sm + 128 * PJP;     // [128][PJP]  W tile, k-major rows

    float* out = g_qkv[which];
    const int tid  = threadIdx.x;
    const int lane = tid & 31;
    const int warp = tid >> 5;
    const int wm   = warp & 3;      // 0..3
    const int wn   = warp >> 2;     // 0..1
    const int m0   = blockIdx.y * 128;
    const int n0   = blockIdx.x * 128;

    float acc[2][8][4];
#pragma unroll
    for (int mt = 0; mt < 2; mt++)
#pragma unroll
        for (int nt = 0; nt < 8; nt++)
#pragma unroll
            for (int j = 0; j < 4; j++) acc[mt][nt][j] = 0.0f;

    const int lg = lane >> 2;       // 0..7
    const int lk = lane & 3;        // 0..3

    for (int k0 = 0; k0 < DIN; k0 += 64) {
        __syncthreads();
        // load A and B tiles: 128 rows x 64 k each (2048 float4 each)
#pragma unroll
        for (int i = 0; i < 8; i++) {
            int f   = tid + i * 256;
            int row = f >> 4;
            int c4  = (f & 15) * 4;
            float4 av = *(const float4*)(X + (size_t)(m0 + row) * DIN + k0 + c4);
            float* da = As + row * PJP + c4;
            da[0] = f2tf32(av.x); da[1] = f2tf32(av.y);
            da[2] = f2tf32(av.z); da[3] = f2tf32(av.w);
            float4 bv = *(const float4*)(W + (size_t)(n0 + row) * DIN + k0 + c4);
            float* db = Bs + row * PJP + c4;
            db[0] = f2tf32(bv.x); db[1] = f2tf32(bv.y);
            db[2] = f2tf32(bv.z); db[3] = f2tf32(bv.w);
        }
        __syncthreads();

#pragma unroll
        for (int ks = 0; ks < 8; ks++) {
            int kk = ks * 8 + lk;
            unsigned a[2][4];
#pragma unroll
            for (int mt = 0; mt < 2; mt++) {
                int r = wm * 32 + mt * 16 + lg;
                a[mt][0] = __float_as_uint(As[r * PJP + kk]);
                a[mt][1] = __float_as_uint(As[(r + 8) * PJP + kk]);
                a[mt][2] = __float_as_uint(As[r * PJP + kk + 4]);
                a[mt][3] = __float_as_uint(As[(r + 8) * PJP + kk + 4]);
            }
#pragma unroll
            for (int nt = 0; nt < 8; nt++) {
                int c = wn * 64 + nt * 8 + lg;
                unsigned b0 = __float_as_uint(Bs[c * PJP + kk]);
                unsigned b1 = __float_as_uint(Bs[c * PJP + kk + 4]);
                mma_tf32(acc[0][nt], a[0][0], a[0][1], a[0][2], a[0][3], b0, b1);
                mma_tf32(acc[1][nt], a[1][0], a[1][1], a[1][2], a[1][3], b0, b1);
            }
        }
    }

    // Epilogue: remap (m, n) -> [b*16+h][nseq][d]
#pragma unroll
    for (int mt = 0; mt < 2; mt++) {
#pragma unroll
        for (int nt = 0; nt < 8; nt++) {
            int m = m0 + wm * 32 + mt * 16 + lg;
            int n = n0 + wn * 64 + nt * 8 + lk * 2;
            int bb = m >> 11, ns = m & (N_ - 1);
            int h = n >> 6, d = n & 63;
            size_t base0 = (((size_t)(bb * NH_ + h)) * N_ + ns) * HD_ + d;
            out[base0]     = acc[mt][nt][0];
            out[base0 + 1] = acc[mt][nt][1];
            size_t base1 = (((size_t)(bb * NH_ + h)) * N_ + ns + 8) * HD_ + d;
            out[base1]     = acc[mt][nt][2];
            out[base1 + 1] = acc[mt][nt][3];
        }
    }
}

// ---------------------------------------------------------------------------
// Flash attention (tf32 mma): Q tile 128 rows, KV tiles 64.
// 8 warps; warp w owns S/O rows [16w, 16w+16) -> softmax rows never cross
// warps (only the 4-lane shfl group). P round-trips through smem with
// __syncwarp only.
// ---------------------------------------------------------------------------
#define QP 68
#define VP 72
#define ATT_SMEM ((128 * QP + 64 * QP + 64 * VP + 128 * QP) * 4)

__global__ __launch_bounds__(256) void attn_mma(float* __restrict__ out) {
    extern __shared__ float sm[];
    float* Qs = sm;                     // [128][QP]
    float* Ks = Qs + 128 * QP;          // [64][QP]
    float* Vs = Ks + 64 * QP;           // [64][VP]
    float* Ps = Vs + 64 * VP;           // [128][QP]

    const int tid  = threadIdx.x;
    const int lane = tid & 31;
    const int warp = tid >> 5;
    const int qb = blockIdx.x;          // 0..15
    const int bh = blockIdx.y;          // 0..63
    const int lg = lane >> 2;           // 0..7
    const int lk = lane & 3;            // 0..3
    const int r0 = warp * 16 + lg;      // this thread's first S row

    const float* Q = g_qkv[0] + ((size_t)bh * N_ + qb * 128) * HD_;
    const float* K = g_qkv[1] + (size_t)bh * N_ * HD_;
    const float* V = g_qkv[2] + (size_t)bh * N_ * HD_;

    // Load Q tile (128x64)
#pragma unroll
    for (int i = 0; i < 8; i++) {
        int f = tid + i * 256;          // 2048 float4
        int row = f >> 4;
        int c4 = (f & 15) * 4;
        float4 v = *(const float4*)(Q + (size_t)row * HD_ + c4);
        float* d = Qs + row * QP + c4;
        d[0] = f2tf32(v.x); d[1] = f2tf32(v.y);
        d[2] = f2tf32(v.z); d[3] = f2tf32(v.w);
    }

    float o[8][4];
#pragma unroll
    for (int nt = 0; nt < 8; nt++)
#pragma unroll
        for (int j = 0; j < 4; j++) o[nt][j] = 0.0f;
    float m0s = -1e30f, m1s = -1e30f, l0s = 0.0f, l1s = 0.0f;

    for (int kt = 0; kt < N_ / 64; kt++) {
        __syncthreads();
        // Load K, V tiles (64x64 each = 1024 float4 each)
#pragma unroll
        for (int i = 0; i < 4; i++) {
            int f = tid + i * 256;
            int row = f >> 4;
            int c4 = (f & 15) * 4;
            float4 kv = *(const float4*)(K + (size_t)(kt * 64 + row) * HD_ + c4);
            float* dk = Ks + row * QP + c4;
            dk[0] = f2tf32(kv.x); dk[1] = f2tf32(kv.y);
            dk[2] = f2tf32(kv.z); dk[3] = f2tf32(kv.w);
            float4 vv = *(const float4*)(V + (size_t)(kt * 64 + row) * HD_ + c4);
            float* dv = Vs + row * VP + c4;
            dv[0] = f2tf32(vv.x); dv[1] = f2tf32(vv.y);
            dv[2] = f2tf32(vv.z); dv[3] = f2tf32(vv.w);
        }
        __syncthreads();

        // S = Q K^T (warp rows [16w,16w+16), full 64 cols)
        float s[8][4];
#pragma unroll
        for (int nt = 0; nt < 8; nt++)
#pragma unroll
            for (int j = 0; j < 4; j++) s[nt][j] = 0.0f;

#pragma unroll
        for (int ks = 0; ks < 8; ks++) {
            int kk = ks * 8 + lk;
            unsigned a0 = __float_as_uint(Qs[r0 * QP + kk]);
            unsigned a1 = __float_as_uint(Qs[(r0 + 8) * QP + kk]);
            unsigned a2 = __float_as_uint(Qs[r0 * QP + kk + 4]);
            unsigned a3 = __float_as_uint(Qs[(r0 + 8) * QP + kk + 4]);
#pragma unroll
            for (int nt = 0; nt < 8; nt++) {
                int c = nt * 8 + lg;
                unsigned b0 = __float_as_uint(Ks[c * QP + kk]);
                unsigned b1 = __float_as_uint(Ks[c * QP + kk + 4]);
                mma_tf32(s[nt], a0, a1, a2, a3, b0, b1);
            }
        }

        // scale + row max (row r0 in c0/c1, row r0+8 in c2/c3)
        float vm0 = -1e30f, vm1 = -1e30f;
#pragma unroll
        for (int nt = 0; nt < 8; nt++) {
            s[nt][0] *= 0.125f; s[nt][1] *= 0.125f;
            s[nt][2] *= 0.125f; s[nt][3] *= 0.125f;
            vm0 = fmaxf(vm0, fmaxf(s[nt][0], s[nt][1]));
            vm1 = fmaxf(vm1, fmaxf(s[nt][2], s[nt][3]));
        }
        vm0 = fmaxf(vm0, __shfl_xor_sync(0xffffffffu, vm0, 1));
        vm0 = fmaxf(vm0, __shfl_xor_sync(0xffffffffu, vm0, 2));
        vm1 = fmaxf(vm1, __shfl_xor_sync(0xffffffffu, vm1, 1));
        vm1 = fmaxf(vm1, __shfl_xor_sync(0xffffffffu, vm1, 2));

        float nm0 = fmaxf(m0s, vm0), nm1 = fmaxf(m1s, vm1);
        float corr0 = __expf(m0s - nm0), corr1 = __expf(m1s - nm1);
        m0s = nm0; m1s = nm1;

        float rs0 = 0.0f, rs1 = 0.0f;
#pragma unroll
        for (int nt = 0; nt < 8; nt++) {
            s[nt][0] = __expf(s[nt][0] - nm0);
            s[nt][1] = __expf(s[nt][1] - nm0);
            s[nt][2] = __expf(s[nt][2] - nm1);
            s[nt][3] = __expf(s[nt][3] - nm1);
            rs0 += s[nt][0] + s[nt][1];
            rs1 += s[nt][2] + s[nt][3];
        }
        rs0 += __shfl_xor_sync(0xffffffffu, rs0, 1);
        rs0 += __shfl_xor_sync(0xffffffffu, rs0, 2);
        rs1 += __shfl_xor_sync(0xffffffffu, rs1, 1);
        rs1 += __shfl_xor_sync(0xffffffffu, rs1, 2);
        l0s = l0s * corr0 + rs0;
        l1s = l1s * corr1 + rs1;

#pragma unroll
        for (int nt = 0; nt < 8; nt++) {
            o[nt][0] *= corr0; o[nt][1] *= corr0;
            o[nt][2] *= corr1; o[nt][3] *= corr1;
        }

        // P -> smem (warp-local rows), then O += P V
#pragma unroll
        for (int nt = 0; nt < 8; nt++) {
            int c = nt * 8 + lk * 2;
            Ps[r0 * QP + c]           = f2tf32(s[nt][0]);
            Ps[r0 * QP + c + 1]       = f2tf32(s[nt][1]);
            Ps[(r0 + 8) * QP + c]     = f2tf32(s[nt][2]);
            Ps[(r0 + 8) * QP + c + 1] = f2tf32(s[nt][3]);
        }
        __syncwarp();

#pragma unroll
        for (int ks = 0; ks < 8; ks++) {
            int kk = ks * 8 + lk;
            unsigned a0 = __float_as_uint(Ps[r0 * QP + kk]);
            unsigned a1 = __float_as_uint(Ps[(r0 + 8) * QP + kk]);
            unsigned a2 = __float_as_uint(Ps[r0 * QP + kk + 4]);
            unsigned a3 = __float_as_uint(Ps[(r0 + 8) * QP + kk + 4]);
#pragma unroll
            for (int nt = 0; nt < 8; nt++) {
                int c = nt * 8 + lg;
                unsigned b0 = __float_as_uint(Vs[kk * VP + c]);
                unsigned b1 = __float_as_uint(Vs[(kk + 4) * VP + c]);
                mma_tf32(o[nt], a0, a1, a2, a3, b0, b1);
            }
        }
    }

    // Final normalize + write out[b][n][h*64+d]
    float inv0 = 1.0f / l0s, inv1 = 1.0f / l1s;
    const int bb = bh >> 4;
    const int h  = bh & 15;
    const int n0 = qb * 128 + r0;
#pragma unroll
    for (int nt = 0; nt < 8; nt++) {
        int d = h * HD_ + nt * 8 + lk * 2;
        size_t base0 = ((size_t)bb * N_ + n0) * DMODEL + d;
        out[base0]     = o[nt][0] * inv0;
        out[base0 + 1] = o[nt][1] * inv0;
        size_t base1 = ((size_t)bb * N_ + n0 + 8) * DMODEL + d;
        out[base1]     = o[nt][2] * inv1;
        out[base1 + 1] = o[nt][3] * inv1;
    }
}

// ---------------------------------------------------------------------------
// Launch
// ---------------------------------------------------------------------------
extern "C" void kernel_launch(void* const* d_in, const int* in_sizes, int n_in,
                              void* d_out, int out_size) {
    const float* x  = (const float*)d_in[0];
    const float* Wq = (const float*)d_in[2];
    const float* Wk = (const float*)d_in[3];
    const float* Wv = (const float*)d_in[4];
    float* out = (float*)d_out;
    (void)in_sizes; (void)n_in; (void)out_size;

    cudaFuncSetAttribute(proj_mma,
                         cudaFuncAttributeMaxDynamicSharedMemorySize, PROJ_SMEM);
    cudaFuncSetAttribute(attn_mma,
                         cudaFuncAttributeMaxDynamicSharedMemorySize, ATT_SMEM);

    dim3 pgrid(DMODEL / 128, (B_ * N_) / 128);   // (8, 64)
    proj_mma<<<pgrid, 256, PROJ_SMEM>>>(x, Wq, 0);
    proj_mma<<<pgrid, 256, PROJ_SMEM>>>(x, Wk, 1);
    proj_mma<<<pgrid, 256, PROJ_SMEM>>>(x, Wv, 2);

    dim3 agrid(N_ / 128, BH_);                   // (16, 64)
    attn_mma<<<agrid, 256, ATT_SMEM>>>(out);
}

// round 4
// speedup vs baseline: 3.2385x; 1.0436x over previous
#include <cuda_runtime.h>
#include <cstdint>

#define B_     4
#define N_     2048
#define DIN    1024
#define NH_    16
#define HD_    64
#define BH_    64
#define DMODEL 1024

// Scratch buffers (device globals; no allocation).
__device__ float g_qkv[3][(size_t)BH_ * N_ * HD_];   // Q/K permuted, V natural
__device__ float g_x[(size_t)B_ * N_ * DIN];         // rounded+permuted X
__device__ float g_w[3][(size_t)DMODEL * DIN];       // rounded+permuted W

// ---------------------------------------------------------------------------
// Helpers
// ---------------------------------------------------------------------------
__device__ __forceinline__ float f2tf32(float f) {
    unsigned u;
    asm("cvt.rna.tf32.f32 %0, %1;" : "=r"(u) : "f"(f));
    return __uint_as_float(u);
}

__device__ __forceinline__ void mma_tf32(float c[4],
                                         float a0, float a1, float a2, float a3,
                                         float b0, float b1) {
    asm volatile(
        "mma.sync.aligned.m16n8k8.row.col.f32.tf32.tf32.f32 "
        "{%0,%1,%2,%3}, {%4,%5,%6,%7}, {%8,%9}, {%0,%1,%2,%3};"
        : "+f"(c[0]), "+f"(c[1]), "+f"(c[2]), "+f"(c[3])
        : "r"(__float_as_uint(a0)), "r"(__float_as_uint(a1)),
          "r"(__float_as_uint(a2)), "r"(__float_as_uint(a3)),
          "r"(__float_as_uint(b0)), "r"(__float_as_uint(b1)));
}

// interleave within 8-col group: col c -> pos, pairing (kk, kk+4) adjacently
__device__ __forceinline__ int ipos(int c) {
    return (c & ~7) + 2 * (c & 3) + ((c >> 2) & 1);
}

__device__ __forceinline__ void cpa16(uint32_t dst, const float* src) {
    asm volatile("cp.async.ca.shared.global [%0], [%1], 16;"
                 :: "r"(dst), "l"(src));
}
#define CP_COMMIT() asm volatile("cp.async.commit_group;")
#define CP_WAIT(n)  asm volatile("cp.async.wait_group %0;" :: "n"(n))

// ---------------------------------------------------------------------------
// Prep: round to tf32 (rna) + permute low-3-bits of last dim.
// which: 0 -> g_x, 1..3 -> g_w[which-1]
// ---------------------------------------------------------------------------
__global__ __launch_bounds__(256) void prep_kernel(const float* __restrict__ src,
                                                   int which, int n4) {
    float* dst = (which == 0) ? g_x : g_w[which - 1];
    int i = blockIdx.x * blockDim.x + threadIdx.x;
    if (i >= n4) return;
    float4 v = ((const float4*)src)[i];
    int base = i * 4;
    int g = base & ~7;
    int w0 = base & 7;                 // 0 or 4
    float vv[4] = {v.x, v.y, v.z, v.w};
#pragma unroll
    for (int t = 0; t < 4; t++) {
        int w = w0 + t;
        dst[g + 2 * (w & 3) + ((w >> 2) & 1)] = f2tf32(vv[t]);
    }
}

// ---------------------------------------------------------------------------
// Projection GEMM: C = X * W^T -> g_qkv[z], remapped to [bh][n][d].
// CTA 128x128, k-chunk 32, 3-stage cp.async pipeline, 8 warps 4m x 2n.
// Smem pitch 36 floats; fragment pairs loaded as float2 (globals pre-permuted).
// z<2 (Q,K): output head-dim permuted; z==2 (V): natural.
// ---------------------------------------------------------------------------
#define PP    36
#define PSTG  (128 * PP)                  // floats per matrix per stage
#define PROJ_SMEM (3 * 2 * PSTG * 4)      // 110592 B
#define NCH   (DIN / 32)                  // 32 chunks

__global__ __launch_bounds__(256, 2) void proj_mma() {
    extern __shared__ float sm[];
    const int tid  = threadIdx.x;
    const int lane = tid & 31;
    const int warp = tid >> 5;
    const int wm   = warp & 3;
    const int wn   = warp >> 2;
    const int m0   = blockIdx.y * 128;
    const int n0   = blockIdx.x * 128;
    const int z    = blockIdx.z;
    const int lg   = lane >> 2;
    const int lk   = lane & 3;

    const float* Xg = g_x + (size_t)m0 * DIN;
    const float* Wg = g_w[z] + (size_t)n0 * DIN;
    float* out = g_qkv[z];

    const uint32_t smb = (uint32_t)__cvta_generic_to_shared(sm);
    const int frow = tid >> 3;            // 0..31 fill row block? (f>>3 below)
    (void)frow;

    // issue one k-chunk into stage c%3
    auto issue = [&](int c) {
        uint32_t sA = smb + (uint32_t)((c % 3) * 2 * PSTG) * 4;
        uint32_t sB = sA + (uint32_t)PSTG * 4;
        const float* xs = Xg + c * 32;
        const float* ws = Wg + c * 32;
#pragma unroll
        for (int i = 0; i < 4; i++) {
            int f = tid + i * 256;        // 0..1023
            int row = f >> 3;
            int c4 = (f & 7) * 4;
            cpa16(sA + (uint32_t)(row * PP + c4) * 4, xs + (size_t)row * DIN + c4);
            cpa16(sB + (uint32_t)(row * PP + c4) * 4, ws + (size_t)row * DIN + c4);
        }
    };

    float acc[2][8][4];
#pragma unroll
    for (int mt = 0; mt < 2; mt++)
#pragma unroll
        for (int nt = 0; nt < 8; nt++)
#pragma unroll
            for (int j = 0; j < 4; j++) acc[mt][nt][j] = 0.0f;

    issue(0); CP_COMMIT();
    issue(1); CP_COMMIT();
    issue(2); CP_COMMIT();
    CP_WAIT(2);
    __syncthreads();

    for (int c = 0; c < NCH; c++) {
        const float* As = sm + (c % 3) * 2 * PSTG;
        const float* Bs = As + PSTG;
        const int r0 = wm * 32 + lg;
        const int c0 = wn * 64 + lg;
#pragma unroll
        for (int ks = 0; ks < 4; ks++) {
            int kp = ks * 8 + 2 * lk;
            float2 aA0 = *(const float2*)(As + r0 * PP + kp);
            float2 aA1 = *(const float2*)(As + (r0 + 8) * PP + kp);
            float2 aB0 = *(const float2*)(As + (r0 + 16) * PP + kp);
            float2 aB1 = *(const float2*)(As + (r0 + 24) * PP + kp);
#pragma unroll
            for (int nt = 0; nt < 8; nt++) {
                float2 b = *(const float2*)(Bs + (c0 + nt * 8) * PP + kp);
                mma_tf32(acc[0][nt], aA0.x, aA1.x, aA0.y, aA1.y, b.x, b.y);
                mma_tf32(acc[1][nt], aB0.x, aB1.x, aB0.y, aB1.y, b.x, b.y);
            }
        }
        __syncthreads();
        if (c + 3 < NCH) {
            issue(c + 3); CP_COMMIT();
            CP_WAIT(2);
        } else {
            CP_WAIT(0);
        }
        __syncthreads();
    }

    // Epilogue: (m, n) -> [b*16+h][nseq][d]; Q/K permuted along d.
#pragma unroll
    for (int mt = 0; mt < 2; mt++) {
#pragma unroll
        for (int nt = 0; nt < 8; nt++) {
            int m = m0 + wm * 32 + mt * 16 + lg;
            int n = n0 + wn * 64 + nt * 8 + lk * 2;
            int bb = m >> 11, ns = m & (N_ - 1);
            int h = n >> 6, d = n & 63;
            int d0, d1;
            if (z < 2) { d0 = ipos(d); d1 = d0 + 2; }
            else       { d0 = d;       d1 = d + 1; }
            size_t rb0 = (((size_t)(bb * NH_ + h)) * N_ + ns) * HD_;
            out[rb0 + d0] = f2tf32(acc[mt][nt][0]);
            out[rb0 + d1] = f2tf32(acc[mt][nt][1]);
            size_t rb1 = (((size_t)(bb * NH_ + h)) * N_ + ns + 8) * HD_;
            out[rb1 + d0] = f2tf32(acc[mt][nt][2]);
            out[rb1 + d1] = f2tf32(acc[mt][nt][3]);
        }
    }
}

// ---------------------------------------------------------------------------
// Flash attention: Q tile 128, KV tiles 64, cp.async 2-stage KV pipeline.
// Q fragments hoisted to registers; Qs smem reused as Ps (interleaved).
// K permuted (float2 b-frags), V natural (conflict-free scalar b-frags).
// ---------------------------------------------------------------------------
#define QSP 68
#define KSP 68
#define VSP 72
#define AQ_FL   (128 * QSP)               // 8704
#define AK_FL   (64 * KSP)                // 4352
#define AV_FL   (64 * VSP)                // 4608
#define ATT_SMEM ((AQ_FL + 2 * AK_FL + 2 * AV_FL) * 4)   // 106496 B

__global__ __launch_bounds__(256, 2) void attn_mma(float* __restrict__ out) {
    extern __shared__ float sm[];
    float* Qs  = sm;                        // staging, reused as Ps
    float* Ks0 = sm + AQ_FL;
    float* Ks1 = Ks0 + AK_FL;
    float* Vs0 = Ks1 + AK_FL;
    float* Vs1 = Vs0 + AV_FL;

    const int tid  = threadIdx.x;
    const int lane = tid & 31;
    const int warp = tid >> 5;
    const int qb = blockIdx.x;
    const int bh = blockIdx.y;
    const int lg = lane >> 2;
    const int lk = lane & 3;
    const int r0 = warp * 16 + lg;

    const float* Qg = g_qkv[0] + ((size_t)bh * N_ + qb * 128) * HD_;
    const float* Kg = g_qkv[1] + (size_t)bh * N_ * HD_;
    const float* Vg = g_qkv[2] + (size_t)bh * N_ * HD_;

    const uint32_t smb  = (uint32_t)__cvta_generic_to_shared(sm);
    const uint32_t sQ   = smb;
    const uint32_t sK[2] = { smb + AQ_FL * 4, smb + (AQ_FL + AK_FL) * 4 };
    const uint32_t sV[2] = { smb + (AQ_FL + 2 * AK_FL) * 4,
                             smb + (AQ_FL + 2 * AK_FL + AV_FL) * 4 };

    auto issueKV = [&](int kt) {
        int st = kt & 1;
        const float* kp = Kg + (size_t)(kt * 64) * HD_;
        const float* vp = Vg + (size_t)(kt * 64) * HD_;
#pragma unroll
        for (int i = 0; i < 4; i++) {
            int f = tid + i * 256;         // 0..1023
            int row = f >> 4;
            int c4 = (f & 15) * 4;
            cpa16(sK[st] + (uint32_t)(row * KSP + c4) * 4, kp + (size_t)row * HD_ + c4);
            cpa16(sV[st] + (uint32_t)(row * VSP + c4) * 4, vp + (size_t)row * HD_ + c4);
        }
    };

    // prologue: Q + KV0 (group 0), KV1 (group 1)
    {
#pragma unroll
        for (int i = 0; i < 8; i++) {
            int f = tid + i * 256;         // 0..2047
            int row = f >> 4;
            int c4 = (f & 15) * 4;
            cpa16(sQ + (uint32_t)(row * QSP + c4) * 4, Qg + (size_t)row * HD_ + c4);
        }
        issueKV(0); CP_COMMIT();
        issueKV(1); CP_COMMIT();
        CP_WAIT(1);
        __syncthreads();
    }

    // hoist Q fragments (globals pre-permuted -> float2 pairs)
    float2 qf0[8], qf1[8];
#pragma unroll
    for (int ks = 0; ks < 8; ks++) {
        qf0[ks] = *(const float2*)(Qs + r0 * QSP + ks * 8 + 2 * lk);
        qf1[ks] = *(const float2*)(Qs + (r0 + 8) * QSP + ks * 8 + 2 * lk);
    }
    __syncthreads();                       // Qs now reusable as Ps
    float* Ps = Qs;

    float o[8][4];
#pragma unroll
    for (int nt = 0; nt < 8; nt++)
#pragma unroll
        for (int j = 0; j < 4; j++) o[nt][j] = 0.0f;
    float m0s = -1e30f, m1s = -1e30f, l0s = 0.0f, l1s = 0.0f;

    const int pc0 = ipos(2 * lk);          // P store base position in group
    for (int kt = 0; kt < N_ / 64; kt++) {
        const float* Ksr = (kt & 1) ? Ks1 : Ks0;
        const float* Vsr = (kt & 1) ? Vs1 : Vs0;

        // S = Q K^T
        float s[8][4];
#pragma unroll
        for (int nt = 0; nt < 8; nt++)
#pragma unroll
            for (int j = 0; j < 4; j++) s[nt][j] = 0.0f;

#pragma unroll
        for (int ks = 0; ks < 8; ks++) {
            int kp = ks * 8 + 2 * lk;
#pragma unroll
            for (int nt = 0; nt < 8; nt++) {
                float2 b = *(const float2*)(Ksr + (nt * 8 + lg) * KSP + kp);
                mma_tf32(s[nt], qf0[ks].x, qf1[ks].x, qf0[ks].y, qf1[ks].y,
                         b.x, b.y);
            }
        }

        // softmax (rows r0 in c0/c1, r0+8 in c2/c3)
        float vm0 = -1e30f, vm1 = -1e30f;
#pragma unroll
        for (int nt = 0; nt < 8; nt++) {
            s[nt][0] *= 0.125f; s[nt][1] *= 0.125f;
            s[nt][2] *= 0.125f; s[nt][3] *= 0.125f;
            vm0 = fmaxf(vm0, fmaxf(s[nt][0], s[nt][1]));
            vm1 = fmaxf(vm1, fmaxf(s[nt][2], s[nt][3]));
        }
        vm0 = fmaxf(vm0, __shfl_xor_sync(0xffffffffu, vm0, 1));
        vm0 = fmaxf(vm0, __shfl_xor_sync(0xffffffffu, vm0, 2));
        vm1 = fmaxf(vm1, __shfl_xor_sync(0xffffffffu, vm1, 1));
        vm1 = fmaxf(vm1, __shfl_xor_sync(0xffffffffu, vm1, 2));

        float nm0 = fmaxf(m0s, vm0), nm1 = fmaxf(m1s, vm1);
        float corr0 = __expf(m0s - nm0), corr1 = __expf(m1s - nm1);
        m0s = nm0; m1s = nm1;

        float rs0 = 0.0f, rs1 = 0.0f;
#pragma unroll
        for (int nt = 0; nt < 8; nt++) {
            s[nt][0] = __expf(s[nt][0] - nm0);
            s[nt][1] = __expf(s[nt][1] - nm0);
            s[nt][2] = __expf(s[nt][2] - nm1);
            s[nt][3] = __expf(s[nt][3] - nm1);
            rs0 += s[nt][0] + s[nt][1];
            rs1 += s[nt][2] + s[nt][3];
        }
        rs0 += __shfl_xor_sync(0xffffffffu, rs0, 1);
        rs0 += __shfl_xor_sync(0xffffffffu, rs0, 2);
        rs1 += __shfl_xor_sync(0xffffffffu, rs1, 1);
        rs1 += __shfl_xor_sync(0xffffffffu, rs1, 2);
        l0s = l0s * corr0 + rs0;
        l1s = l1s * corr1 + rs1;

#pragma unroll
        for (int nt = 0; nt < 8; nt++) {
            o[nt][0] *= corr0; o[nt][1] *= corr0;
            o[nt][2] *= corr1; o[nt][3] *= corr1;
        }

        // P -> smem (warp-local rows, interleaved positions)
#pragma unroll
        for (int nt = 0; nt < 8; nt++) {
            int p = nt * 8 + pc0;
            Ps[r0 * QSP + p]           = f2tf32(s[nt][0]);
            Ps[r0 * QSP + p + 2]       = f2tf32(s[nt][1]);
            Ps[(r0 + 8) * QSP + p]     = f2tf32(s[nt][2]);
            Ps[(r0 + 8) * QSP + p + 2] = f2tf32(s[nt][3]);
        }
        __syncwarp();

        // O += P V
#pragma unroll
        for (int ks = 0; ks < 8; ks++) {
            int kp = ks * 8 + 2 * lk;
            float2 pa0 = *(const float2*)(Ps + r0 * QSP + kp);
            float2 pa1 = *(const float2*)(Ps + (r0 + 8) * QSP + kp);
            const float* v0 = Vsr + (ks * 8 + lk) * VSP + lg;
            const float* v1 = Vsr + (ks * 8 + lk + 4) * VSP + lg;
#pragma unroll
            for (int nt = 0; nt < 8; nt++) {
                mma_tf32(o[nt], pa0.x, pa1.x, pa0.y, pa1.y,
                         v0[nt * 8], v1[nt * 8]);
            }
        }

        __syncthreads();
        if (kt + 2 < N_ / 64) {
            issueKV(kt + 2); CP_COMMIT();
            CP_WAIT(1);
        } else {
            CP_WAIT(0);
        }
        __syncthreads();
    }

    // normalize + write out[b][n][h*64+d] (natural layout)
    float inv0 = 1.0f / l0s, inv1 = 1.0f / l1s;
    const int bb = bh >> 4;
    const int h  = bh & 15;
    const int nn = qb * 128 + r0;
#pragma unroll
    for (int nt = 0; nt < 8; nt++) {
        int d = h * HD_ + nt * 8 + lk * 2;
        size_t base0 = ((size_t)bb * N_ + nn) * DMODEL + d;
        out[base0]     = o[nt][0] * inv0;
        out[base0 + 1] = o[nt][1] * inv0;
        size_t base1 = ((size_t)bb * N_ + nn + 8) * DMODEL + d;
        out[base1]     = o[nt][2] * inv1;
        out[base1 + 1] = o[nt][3] * inv1;
    }
}

// ---------------------------------------------------------------------------
// Launch
// ---------------------------------------------------------------------------
extern "C" void kernel_launch(void* const* d_in, const int* in_sizes, int n_in,
                              void* d_out, int out_size) {
    const float* x  = (const float*)d_in[0];
    const float* Wq = (const float*)d_in[2];
    const float* Wk = (const float*)d_in[3];
    const float* Wv = (const float*)d_in[4];
    float* out = (float*)d_out;
    (void)in_sizes; (void)n_in; (void)out_size;

    cudaFuncSetAttribute(proj_mma,
                         cudaFuncAttributeMaxDynamicSharedMemorySize, PROJ_SMEM);
    cudaFuncSetAttribute(attn_mma,
                         cudaFuncAttributeMaxDynamicSharedMemorySize, ATT_SMEM);

    int nx4 = B_ * N_ * DIN / 4;        // 2,097,152
    int nw4 = DMODEL * DIN / 4;         // 262,144
    prep_kernel<<<nx4 / 256, 256>>>(x, 0, nx4);
    prep_kernel<<<nw4 / 256, 256>>>(Wq, 1, nw4);
    prep_kernel<<<nw4 / 256, 256>>>(Wk, 2, nw4);
    prep_kernel<<<nw4 / 256, 256>>>(Wv, 3, nw4);

    dim3 pgrid(DMODEL / 128, (B_ * N_) / 128, 3);   // (8, 64, 3)
    proj_mma<<<pgrid, 256, PROJ_SMEM>>>();

    dim3 agrid(N_ / 128, BH_);                      // (16, 64)
    attn_mma<<<agrid, 256, ATT_SMEM>>>(out);
}